// round 4
// baseline (speedup 1.0000x reference)
#include <cuda_runtime.h>
#include <cstdint>

#define NTAG      48
#define START_TAG 46
#define STOP_TAG  47
#define BB        128
#define TT        256
#define RS        50                 // padded row stride (floats): conflict-free LDS
#define TILE_ELEMS (NTAG * RS)       // 2400
#define NBUF      4
#define NTHREADS  384                // 12 warps; j = tid>>3, s = tid&7

__device__ float        g_partials[BB];
__device__ unsigned int g_count = 0;

__device__ __forceinline__ void cp_async8(uint32_t dst, const void* src) {
    unsigned long long gsrc;
    asm volatile("cvta.to.global.u64 %0, %1;\n" : "=l"(gsrc) : "l"(src));
    asm volatile("cp.async.ca.shared.global [%0], [%1], 8;\n" :: "r"(dst), "l"(gsrc));
}
__device__ __forceinline__ void cp_commit() {
    asm volatile("cp.async.commit_group;\n" ::: "memory");
}
__device__ __forceinline__ void cp_wait0() {
    asm volatile("cp.async.wait_group 0;\n" ::: "memory");
}
__device__ __forceinline__ void cp_wait1() {
    asm volatile("cp.async.wait_group 1;\n" ::: "memory");
}

// 48x48 f32 tile (192B rows) -> padded SMEM (200B stride). 3 x 8B per thread.
__device__ __forceinline__ void load_tile(uint32_t sbase, const float* g, int tid) {
    const int r0   = tid / 24;
    const int off8 = (tid % 24) * 8;
    #pragma unroll
    for (int it = 0; it < 3; ++it) {
        const int row = r0 + 16 * it;
        cp_async8(sbase + (uint32_t)(row * (RS * 4) + off8),
                  (const char*)g + row * (NTAG * 4) + off8);
    }
}

__device__ __forceinline__ void l2_prefetch_tile(const float* g, int tid) {
    const int r0   = tid / 24;
    const int off8 = (tid % 24) * 8;
    #pragma unroll
    for (int it = 0; it < 3; ++it) {
        const char* p = (const char*)g + (r0 + 16 * it) * (NTAG * 4) + off8;
        asm volatile("prefetch.global.L2 [%0];" :: "l"(p));
    }
}

// Convert raw tile to exp(tile) in place (2304 valid elems, 6 per thread);
// capture the raw gold value for target index tg before overwriting.
__device__ __forceinline__ void convert_tile(float* buf, int tg, float* goldAcc, int tid) {
    const int e0  = tid * 6;                 // never crosses a row (48 % 6 == 0)
    const int row = e0 / NTAG;
    float* bp = buf + row * RS + (e0 % NTAG);
    #pragma unroll
    for (int k = 0; k < 6; ++k) {
        const float v = bp[k];
        if (e0 + k == tg) *goldAcc += v;
        bp[k] = __expf(v);
    }
}

__global__ void __launch_bounds__(NTHREADS, 1) viterbi_fwd(
    const float* __restrict__ feats,
    const void* __restrict__ targets_raw,
    const void* __restrict__ lengths_raw,
    float* __restrict__ out)
{
    __shared__ __align__(16) float tiles[NBUF][TILE_ELEMS];
    __shared__ float P[2][NTAG];
    __shared__ float s_inv[2];
    __shared__ int   s_tgt[TT];
    __shared__ float s_red[NTHREADS];
    __shared__ int   s_isLast;

    const int b   = blockIdx.x;
    const int tid = threadIdx.x;

    // dtype probe: a genuine int64 length[0] lies in [1,256]; int32-misread >= 2^32.
    const long long probe = ((const long long*)lengths_raw)[0];
    const bool is64 = (probe >= 1 && probe <= TT);

    int len = is64 ? (int)((const long long*)lengths_raw)[b]
                   : ((const int*)lengths_raw)[b];
    if (len < 1)  len = 1;
    if (len > TT) len = TT;
    const float* fb = feats + (size_t)b * TT * (NTAG * NTAG);

    uint32_t tbase[NBUF];
    #pragma unroll
    for (int i = 0; i < NBUF; ++i)
        tbase[i] = (uint32_t)__cvta_generic_to_shared(&tiles[i][0]);

    for (int c = tid; c < TT; c += NTHREADS) {
        int v = is64 ? (int)((const long long*)targets_raw)[(size_t)b * TT + c]
                     : ((const int*)targets_raw)[(size_t)b * TT + c];
        if (v < 0) v = 0;
        if (v >= NTAG * NTAG) v = NTAG * NTAG - 1;
        s_tgt[c] = v;
    }

    // Prologue: prefetch up to NBUF tiles; wait so tiles 0..2 are resident.
    const int npre = (len < NBUF) ? len : NBUF;
    for (int p = 0; p < npre; ++p) {
        load_tile(tbase[p], fb + (size_t)p * (NTAG * NTAG), tid);
        cp_commit();
    }
    if (4 < len) l2_prefetch_tile(fb + (size_t)4 * (NTAG * NTAG), tid);
    if (5 < len) l2_prefetch_tile(fb + (size_t)5 * (NTAG * NTAG), tid);
    if (npre == NBUF) cp_wait1(); else cp_wait0();
    __syncthreads();

    // init: P_0[j] = exp(features[b,0,START,j]); gold for t=0 from raw tile 0.
    float p0reg = 0.0f;
    if (tid < NTAG) {
        p0reg = __expf(tiles[0][START_TAG * RS + tid]);
        P[0][tid] = p0reg;
    }
    float goldAcc = 0.0f;
    float A = 0.0f;                       // meaningful on tid 0 only
    if (tid == 0) {
        const int tg = s_tgt[0];
        goldAcc = tiles[0][(tg / NTAG) * RS + (tg % NTAG)];
        s_inv[1] = 1.0f / p0reg;          // scale for step t=1 (reads s_inv[t&1])
        if (len > 1) A = __logf(p0reg);
    }
    // convert tile 1 in place (gold for t=1 captured before overwrite)
    if (len > 1) convert_tile(&tiles[1][0], s_tgt[1], &goldAcc, tid);
    __syncthreads();

    const int j = tid >> 3;               // destination tag
    const int s = tid & 7;                // source slice (6 each)
    int cur = 0;

    for (int t = 1; t < len; ++t) {
        const float* E   = &tiles[t & (NBUF - 1)][0];
        const float  inv = s_inv[t & 1];

        float acc = 0.0f;
        #pragma unroll
        for (int k = 0; k < 6; ++k) {
            const int i = s * 6 + k;
            acc += E[i * RS + j] * P[cur][i];
        }
        acc *= inv;
        acc += __shfl_xor_sync(0xffffffffu, acc, 1);
        acc += __shfl_xor_sync(0xffffffffu, acc, 2);
        acc += __shfl_xor_sync(0xffffffffu, acc, 4);

        if (s == 0) P[cur ^ 1][j] = acc;
        if (tid == 0) {                   // j==0 group: acc == q_0
            s_inv[(t + 1) & 1] = __frcp_rn(acc);
            if (t < len - 1) A += __logf(acc);
        }

        if (t + 1 < len) convert_tile(&tiles[(t + 1) & (NBUF - 1)][0],
                                      s_tgt[t + 1], &goldAcc, tid);
        if (t + 3 < len) {
            load_tile(tbase[(t + 3) & (NBUF - 1)], fb + (size_t)(t + 3) * (NTAG * NTAG), tid);
            cp_commit();
        }
        if (t + 5 < len) l2_prefetch_tile(fb + (size_t)(t + 5) * (NTAG * NTAG), tid);

        if (t + 3 < len) cp_wait1(); else cp_wait0();   // tile t+2 resident
        __syncthreads();
        cur ^= 1;
    }

    // gold reduction across 384 threads (fixed order, deterministic)
    s_red[tid] = goldAcc;
    __syncthreads();
    if (tid < 128) s_red[tid] += s_red[tid + 128] + s_red[tid + 256];
    __syncthreads();
    #pragma unroll
    for (int st = 64; st > 0; st >>= 1) {
        if (tid < st) s_red[tid] += s_red[tid + st];
        __syncthreads();
    }

    if (tid == 0) {
        const float val = (A + __logf(P[cur][STOP_TAG])) - s_red[0];
        g_partials[b] = val;
        __threadfence();
        const unsigned done = atomicAdd(&g_count, 1);
        s_isLast = (done == BB - 1) ? 1 : 0;
    }
    __syncthreads();

    // Last CTA reduces the 128 partials (fixed tree -> deterministic).
    if (s_isLast) {
        if (tid < BB) s_red[tid] = g_partials[tid];
        __syncthreads();
        #pragma unroll
        for (int st = BB / 2; st > 0; st >>= 1) {
            if (tid < st) s_red[tid] += s_red[tid + st];
            __syncthreads();
        }
        if (tid == 0) {
            out[0] = s_red[0];
            g_count = 0;                  // reset for next graph replay
        }
    }
}

extern "C" void kernel_launch(void* const* d_in, const int* in_sizes, int n_in,
                              void* d_out, int out_size) {
    const float* feats   = nullptr;
    const void*  targets = nullptr;
    const void*  lengths = nullptr;
    for (int i = 0; i < n_in; ++i) {
        if (in_sizes[i] == BB * TT * NTAG * NTAG) feats   = (const float*)d_in[i];
        else if (in_sizes[i] == BB * TT)          targets = d_in[i];
        else if (in_sizes[i] == BB)               lengths = d_in[i];
    }
    viterbi_fwd<<<BB, NTHREADS>>>(feats, targets, lengths, (float*)d_out);
}